// round 7
// baseline (speedup 1.0000x reference)
#include <cuda_runtime.h>
#include <math.h>

#define HID 4096
#define HEADS 32
#define DDIM 128
#define IDIM (HEADS * DDIM)            // 4096
#define QKV_ROWS (3 * IDIM)            // 12288
#define TOTAL_ROWS (QKV_ROWS + IDIM + HEADS + HEADS)  // 16448
#define EPS 1e-6f

// ---------------- scratch (no allocation allowed) ----------------
__device__ float g_qkv[QKV_ROWS];
__device__ float g_z[IDIM];
__device__ float g_ab[2 * HEADS];      // a[0:32], b[32:64]
__device__ float g_pre[IDIM];
__device__ float g_state_scratch[HEADS * DDIM * DDIM];
__device__ float g_conv_scratch[QKV_ROWS * 3];

__device__ __forceinline__ float siluf(float x) { return x / (1.f + expf(-x)); }

__device__ __forceinline__ float dot4(float4 a, float4 b) {
    return a.x * b.x + a.y * b.y + a.z * b.z + a.w * b.w;
}

// ---------------- kernel 1: fused matvec (qkv, z, a, b) -------------------
__global__ __launch_bounds__(256) void k_matvec_in(
    const float* __restrict__ Wqkv, const float* __restrict__ Wz,
    const float* __restrict__ Wa,   const float* __restrict__ Wb,
    const float* __restrict__ h)
{
    cudaTriggerProgrammaticLaunchCompletion();

    __shared__ float4 hs[HID / 4];
    const float4* h4 = reinterpret_cast<const float4*>(h);
    for (int i = threadIdx.x; i < HID / 4; i += 256) hs[i] = h4[i];
    __syncthreads();

    int warp = threadIdx.x >> 5;
    int lane = threadIdx.x & 31;
    int row  = blockIdx.x * 8 + warp;

    if (row < TOTAL_ROWS) {
        const float* W;
        float* outp;
        if (row < QKV_ROWS)              { W = Wqkv + (size_t)row * HID;              outp = g_qkv + row; }
        else if (row < QKV_ROWS + IDIM)  { int r = row - QKV_ROWS; W = Wz + (size_t)r * HID; outp = g_z + r; }
        else if (row < QKV_ROWS + IDIM + HEADS) { int r = row - QKV_ROWS - IDIM; W = Wa + (size_t)r * HID; outp = g_ab + r; }
        else                             { int r = row - QKV_ROWS - IDIM - HEADS; W = Wb + (size_t)r * HID; outp = g_ab + HEADS + r; }

        const float4* w4 = reinterpret_cast<const float4*>(W) + lane;

        float4 buf[4];
#pragma unroll
        for (int j = 0; j < 4; j++) buf[j] = __ldcs(w4 + j * 32);

        float a0 = 0.f, a1 = 0.f, a2 = 0.f, a3 = 0.f;
#pragma unroll
        for (int i = 0; i < 8; i++) {
            float4 c0 = buf[0], c1 = buf[1], c2 = buf[2], c3 = buf[3];
            if (i < 7) {
#pragma unroll
                for (int j = 0; j < 4; j++) buf[j] = __ldcs(w4 + ((i + 1) * 4 + j) * 32);
            }
            a0 += dot4(c0, hs[lane + (i * 4 + 0) * 32]);
            a1 += dot4(c1, hs[lane + (i * 4 + 1) * 32]);
            a2 += dot4(c2, hs[lane + (i * 4 + 2) * 32]);
            a3 += dot4(c3, hs[lane + (i * 4 + 3) * 32]);
        }
        float acc = (a0 + a1) + (a2 + a3);
#pragma unroll
        for (int o = 16; o; o >>= 1) acc += __shfl_down_sync(0xFFFFFFFFu, acc, o);
        if (lane == 0) *outp = acc;
    }
}

// ---------------- kernel 2: conv + gating + state update ----------------
__global__ __launch_bounds__(512) void k_state(
    const float* __restrict__ rnn_state, const float* __restrict__ conv_state,
    const float* __restrict__ conv_w,    const float* __restrict__ conv_b,
    const float* __restrict__ A_log,     const float* __restrict__ dt_bias,
    const float* __restrict__ norm_w,
    float* __restrict__ state_out,       float* __restrict__ conv_out)
{
    cudaTriggerProgrammaticLaunchCompletion();

    extern __shared__ float4 Ssm[];            // 4096 float4 = 64 KB
    const int h    = blockIdx.x;
    const int t    = threadIdx.x;
    const int lane = t & 31;
    const int grp  = t >> 5;                   // 0..15

    __shared__ float  kn_sh[DDIM];
    __shared__ float  qn_sh[DDIM];
    __shared__ float  v_sh[DDIM];
    __shared__ float4 part[16][32];
    __shared__ float4 delta4_sh[32];
    __shared__ float  red[32];

    // ---- independent prologue: stage S ----
    const float4* S4 = reinterpret_cast<const float4*>(rnn_state + (size_t)h * DDIM * DDIM);
#pragma unroll
    for (int i = 0; i < 8; i++) Ssm[t + i * 512] = S4[t + i * 512];

    float cs0 = 0.f, cs1 = 0.f, cs2 = 0.f, cw0 = 0.f, cw1 = 0.f, cw2 = 0.f, cw3 = 0.f, cb = 0.f;
    float cs0k = 0.f, cs1k = 0.f, cs2k = 0.f, cw0k = 0.f, cw1k = 0.f, cw2k = 0.f, cw3k = 0.f, cbk = 0.f;
    float cs0v = 0.f, cs1v = 0.f, cs2v = 0.f, cw0v = 0.f, cw1v = 0.f, cw2v = 0.f, cw3v = 0.f, cbv = 0.f;
    int cq = h * DDIM + (t & 127);
    if (t < DDIM) {
        const float* cs = conv_state + (size_t)cq * 3;
        const float* cw = conv_w + (size_t)cq * 4;
        cs0 = cs[0]; cs1 = cs[1]; cs2 = cs[2];
        cw0 = cw[0]; cw1 = cw[1]; cw2 = cw[2]; cw3 = cw[3]; cb = conv_b[cq];
        const float* csk = conv_state + (size_t)(IDIM + cq) * 3;
        const float* cwk = conv_w + (size_t)(IDIM + cq) * 4;
        cs0k = csk[0]; cs1k = csk[1]; cs2k = csk[2];
        cw0k = cwk[0]; cw1k = cwk[1]; cw2k = cwk[2]; cw3k = cwk[3]; cbk = conv_b[IDIM + cq];
        const float* csv = conv_state + (size_t)(2 * IDIM + cq) * 3;
        const float* cwv = conv_w + (size_t)(2 * IDIM + cq) * 4;
        cs0v = csv[0]; cs1v = csv[1]; cs2v = csv[2];
        cw0v = cwv[0]; cw1v = cwv[1]; cw2v = cwv[2]; cw3v = cwv[3]; cbv = conv_b[2 * IDIM + cq];
    }
    float Alog = A_log[h], dtb = dt_bias[h];

    cudaGridDependencySynchronize();
    __syncthreads();

    float q = 0.f, k = 0.f, v = 0.f;
    if (t < DDIM) {
        float xq = g_qkv[cq];
        float xk = g_qkv[IDIM + cq];
        float xv = g_qkv[2 * IDIM + cq];
        q = siluf(cs0 * cw0 + cs1 * cw1 + cs2 * cw2 + xq * cw3 + cb);
        k = siluf(cs0k * cw0k + cs1k * cw1k + cs2k * cw2k + xk * cw3k + cbk);
        v = siluf(cs0v * cw0v + cs1v * cw1v + cs2v * cw2v + xv * cw3v + cbv);
        v_sh[t] = v;
        float* co = conv_out + (size_t)cq * 3;
        co[0] = cs1; co[1] = cs2; co[2] = xq;
        float* cok = conv_out + (size_t)(IDIM + cq) * 3;
        cok[0] = cs1k; cok[1] = cs2k; cok[2] = xk;
        float* cov = conv_out + (size_t)(2 * IDIM + cq) * 3;
        cov[0] = cs1v; cov[1] = cs2v; cov[2] = xv;
    }
    float sq = q * q, sk = k * k;
#pragma unroll
    for (int o = 16; o; o >>= 1) {
        sq += __shfl_down_sync(0xFFFFFFFFu, sq, o);
        sk += __shfl_down_sync(0xFFFFFFFFu, sk, o);
    }
    if (lane == 0) { red[grp] = sq; red[grp + 16] = sk; }
    __syncthreads();
    float sqt = red[0] + red[1] + red[2] + red[3];
    float skt = red[16] + red[17] + red[18] + red[19];
    if (t < DDIM) {
        qn_sh[t] = q / fmaxf(sqrtf(sqt), EPS) * 0.08838834764831845f;
        kn_sh[t] = k / fmaxf(sqrtf(skt), EPS);
    }

    float beta  = 1.f / (1.f + expf(-g_ab[HEADS + h]));
    float arg   = g_ab[h] + dtb;
    float sp    = (arg > 20.f) ? arg : log1pf(expf(arg));
    float decay = expf(-expf(Alog) * sp);
    __syncthreads();

    float4 kv = make_float4(0.f, 0.f, 0.f, 0.f);
#pragma unroll
    for (int j = 0; j < 8; j++) {
        int d = grp * 8 + j;
        float4 s = Ssm[d * 32 + lane];
        float kd = kn_sh[d];
        kv.x += s.x * kd; kv.y += s.y * kd; kv.z += s.z * kd; kv.w += s.w * kd;
    }
    part[grp][lane] = kv;
    __syncthreads();

    if (t < 32) {
        float4 kvt = make_float4(0.f, 0.f, 0.f, 0.f);
#pragma unroll
        for (int g = 0; g < 16; g++) {
            float4 p = part[g][lane];
            kvt.x += p.x; kvt.y += p.y; kvt.z += p.z; kvt.w += p.w;
        }
        float4 d4;
        d4.x = (v_sh[lane * 4 + 0] - kvt.x * decay) * beta;
        d4.y = (v_sh[lane * 4 + 1] - kvt.y * decay) * beta;
        d4.z = (v_sh[lane * 4 + 2] - kvt.z * decay) * beta;
        d4.w = (v_sh[lane * 4 + 3] - kvt.w * decay) * beta;
        delta4_sh[lane] = d4;
    }
    __syncthreads();

    float4* So4 = reinterpret_cast<float4*>(state_out + (size_t)h * DDIM * DDIM);
    float4 delta = delta4_sh[lane];
    float4 core = make_float4(0.f, 0.f, 0.f, 0.f);
#pragma unroll
    for (int j = 0; j < 8; j++) {
        int d = grp * 8 + j;
        float4 s = Ssm[d * 32 + lane];
        float kd = kn_sh[d], qd = qn_sh[d];
        s.x = s.x * decay + kd * delta.x;
        s.y = s.y * decay + kd * delta.y;
        s.z = s.z * decay + kd * delta.z;
        s.w = s.w * decay + kd * delta.w;
        So4[d * 32 + lane] = s;
        core.x += s.x * qd; core.y += s.y * qd; core.z += s.z * qd; core.w += s.w * qd;
    }
    part[grp][lane] = core;
    __syncthreads();

    if (t < 32) {
        float4 c = make_float4(0.f, 0.f, 0.f, 0.f);
#pragma unroll
        for (int g = 0; g < 16; g++) {
            float4 p = part[g][lane];
            c.x += p.x; c.y += p.y; c.z += p.z; c.w += p.w;
        }
        float cc = c.x * c.x + c.y * c.y + c.z * c.z + c.w * c.w;
#pragma unroll
        for (int o = 16; o; o >>= 1) cc += __shfl_xor_sync(0xFFFFFFFFu, cc, o);
        float inv = rsqrtf(cc * (1.f / 128.f) + EPS);
        const float4 nw = reinterpret_cast<const float4*>(norm_w)[lane];
        const float4 z4 = reinterpret_cast<const float4*>(g_z + h * DDIM)[lane];
        float4 o4;
        o4.x = nw.x * c.x * inv * siluf(z4.x);
        o4.y = nw.y * c.y * inv * siluf(z4.y);
        o4.z = nw.z * c.z * inv * siluf(z4.z);
        o4.w = nw.w * c.w * inv * siluf(z4.w);
        reinterpret_cast<float4*>(g_pre + h * DDIM)[lane] = o4;
    }
}

// ---------------- kernel 3: output matvec -------------------------------
// Each thread preloads its full 64-float share of the W_out row into
// registers BEFORE the grid dependency sync (streaming, read-once). With PDL
// early launch these DRAM reads overlap k_matvec_in, and W_out crosses LTS
// exactly once. Post-sync work is pure FMA from registers.
__global__ __launch_bounds__(256) void k_matvec_out(
    const float* __restrict__ Wout, float* __restrict__ out)
{
    const int t   = threadIdx.x;
    const int rin = t >> 6;          // row within block: 0..3
    const int tr  = t & 63;          // thread within row: 0..63
    const int row = blockIdx.x * 4 + rin;

    const float4* w4 = reinterpret_cast<const float4*>(Wout + (size_t)row * IDIM) + tr;

    float4 buf[16];
#pragma unroll
    for (int j = 0; j < 16; j++) buf[j] = __ldcs(w4 + j * 64);

    cudaGridDependencySynchronize();

    __shared__ float4 hs[IDIM / 4];
    __shared__ float  red[8];
    const float4* p4 = reinterpret_cast<const float4*>(g_pre);
    for (int i = t; i < IDIM / 4; i += 256) hs[i] = p4[i];
    __syncthreads();

    float a0 = 0.f, a1 = 0.f, a2 = 0.f, a3 = 0.f;
#pragma unroll
    for (int j = 0; j < 16; j += 4) {
        a0 += dot4(buf[j + 0], hs[tr + (j + 0) * 64]);
        a1 += dot4(buf[j + 1], hs[tr + (j + 1) * 64]);
        a2 += dot4(buf[j + 2], hs[tr + (j + 2) * 64]);
        a3 += dot4(buf[j + 3], hs[tr + (j + 3) * 64]);
    }
    float acc = (a0 + a1) + (a2 + a3);
#pragma unroll
    for (int o = 16; o; o >>= 1) acc += __shfl_down_sync(0xFFFFFFFFu, acc, o);
    int warp = t >> 5, lane = t & 31;
    if (lane == 0) red[warp] = acc;
    __syncthreads();
    if (tr == 0) out[row] = red[rin * 2] + red[rin * 2 + 1];
}

// ---------------- launch ----------------
extern "C" void kernel_launch(void* const* d_in, const int* in_sizes, int n_in,
                              void* d_out, int out_size)
{
    const float* hidden     = (const float*)d_in[0];
    const float* rnn_state  = (const float*)d_in[1];
    const float* conv_state = (const float*)d_in[2];
    const float* W_qkv      = (const float*)d_in[3];
    const float* W_z        = (const float*)d_in[4];
    const float* W_a        = (const float*)d_in[5];
    const float* W_b        = (const float*)d_in[6];
    const float* conv_w     = (const float*)d_in[7];
    const float* conv_b     = (const float*)d_in[8];
    const float* A_log      = (const float*)d_in[9];
    const float* dt_bias    = (const float*)d_in[10];
    const float* norm_w     = (const float*)d_in[11];
    const float* W_out      = (const float*)d_in[12];

    float* out = (float*)d_out;

    float* state_out;
    float* conv_out;
    if (out_size >= IDIM + HEADS * DDIM * DDIM + QKV_ROWS * 3) {
        state_out = out + IDIM;
        conv_out  = out + IDIM + HEADS * DDIM * DDIM;
    } else {
        cudaGetSymbolAddress((void**)&state_out, g_state_scratch);
        cudaGetSymbolAddress((void**)&conv_out,  g_conv_scratch);
    }

    const int STATE_SMEM = 64 * 1024;
    static bool attr_done = false;
    if (!attr_done) {
        cudaFuncSetAttribute(k_state, cudaFuncAttributeMaxDynamicSharedMemorySize, STATE_SMEM);
        attr_done = true;
    }

    k_matvec_in<<<(TOTAL_ROWS + 7) / 8, 256>>>(W_qkv, W_z, W_a, W_b, hidden);

    {
        cudaLaunchConfig_t cfg = {};
        cfg.gridDim  = dim3(HEADS, 1, 1);
        cfg.blockDim = dim3(512, 1, 1);
        cfg.dynamicSmemBytes = STATE_SMEM;
        cfg.stream = 0;
        cudaLaunchAttribute at[1];
        at[0].id = cudaLaunchAttributeProgrammaticStreamSerialization;
        at[0].val.programmaticStreamSerializationAllowed = 1;
        cfg.attrs = at;
        cfg.numAttrs = 1;
        cudaLaunchKernelEx(&cfg, k_state, rnn_state, conv_state, conv_w, conv_b,
                           A_log, dt_bias, norm_w, state_out, conv_out);
    }

    {
        cudaLaunchConfig_t cfg = {};
        cfg.gridDim  = dim3(HID / 4, 1, 1);
        cfg.blockDim = dim3(256, 1, 1);
        cfg.dynamicSmemBytes = 0;
        cfg.stream = 0;
        cudaLaunchAttribute at[1];
        at[0].id = cudaLaunchAttributeProgrammaticStreamSerialization;
        at[0].val.programmaticStreamSerializationAllowed = 1;
        cfg.attrs = at;
        cfg.numAttrs = 1;
        cudaLaunchKernelEx(&cfg, k_matvec_out, W_out, out);
    }
}

// round 8
// speedup vs baseline: 1.2342x; 1.2342x over previous
#include <cuda_runtime.h>
#include <math.h>

#define HID 4096
#define HEADS 32
#define DDIM 128
#define IDIM (HEADS * DDIM)            // 4096
#define QKV_ROWS (3 * IDIM)            // 12288
#define TOTAL_ROWS (QKV_ROWS + IDIM + HEADS + HEADS)  // 16448
#define EPS 1e-6f

// ---------------- scratch (no allocation allowed) ----------------
__device__ float g_qkv[QKV_ROWS];
__device__ float g_z[IDIM];
__device__ float g_ab[2 * HEADS];      // a[0:32], b[32:64]
__device__ float g_pre[IDIM];
__device__ float g_state_scratch[HEADS * DDIM * DDIM];
__device__ float g_conv_scratch[QKV_ROWS * 3];

__device__ __forceinline__ float siluf(float x) { return x / (1.f + expf(-x)); }

__device__ __forceinline__ float dot4(float4 a, float4 b) {
    return a.x * b.x + a.y * b.y + a.z * b.z + a.w * b.w;
}

// ---------------- kernel 1: fused matvec (qkv, z, a, b) -------------------
// PDL trigger at the END: dependents only launch during this kernel's tail,
// so its body gets the whole machine (protects the ~75-80% DRAM operating pt).
__global__ __launch_bounds__(256) void k_matvec_in(
    const float* __restrict__ Wqkv, const float* __restrict__ Wz,
    const float* __restrict__ Wa,   const float* __restrict__ Wb,
    const float* __restrict__ h)
{
    __shared__ float4 hs[HID / 4];
    const float4* h4 = reinterpret_cast<const float4*>(h);
    for (int i = threadIdx.x; i < HID / 4; i += 256) hs[i] = h4[i];
    __syncthreads();

    int warp = threadIdx.x >> 5;
    int lane = threadIdx.x & 31;
    int row  = blockIdx.x * 8 + warp;

    if (row < TOTAL_ROWS) {
        const float* W;
        float* outp;
        if (row < QKV_ROWS)              { W = Wqkv + (size_t)row * HID;              outp = g_qkv + row; }
        else if (row < QKV_ROWS + IDIM)  { int r = row - QKV_ROWS; W = Wz + (size_t)r * HID; outp = g_z + r; }
        else if (row < QKV_ROWS + IDIM + HEADS) { int r = row - QKV_ROWS - IDIM; W = Wa + (size_t)r * HID; outp = g_ab + r; }
        else                             { int r = row - QKV_ROWS - IDIM - HEADS; W = Wb + (size_t)r * HID; outp = g_ab + HEADS + r; }

        const float4* w4 = reinterpret_cast<const float4*>(W) + lane;

        float4 buf[4];
#pragma unroll
        for (int j = 0; j < 4; j++) buf[j] = __ldcs(w4 + j * 32);

        float a0 = 0.f, a1 = 0.f, a2 = 0.f, a3 = 0.f;
#pragma unroll
        for (int i = 0; i < 8; i++) {
            float4 c0 = buf[0], c1 = buf[1], c2 = buf[2], c3 = buf[3];
            if (i < 7) {
#pragma unroll
                for (int j = 0; j < 4; j++) buf[j] = __ldcs(w4 + ((i + 1) * 4 + j) * 32);
            }
            a0 += dot4(c0, hs[lane + (i * 4 + 0) * 32]);
            a1 += dot4(c1, hs[lane + (i * 4 + 1) * 32]);
            a2 += dot4(c2, hs[lane + (i * 4 + 2) * 32]);
            a3 += dot4(c3, hs[lane + (i * 4 + 3) * 32]);
        }
        float acc = (a0 + a1) + (a2 + a3);
#pragma unroll
        for (int o = 16; o; o >>= 1) acc += __shfl_down_sync(0xFFFFFFFFu, acc, o);
        if (lane == 0) *outp = acc;
    }

    cudaTriggerProgrammaticLaunchCompletion();
}

// ---------------- kernel 2: conv + gating + state update ----------------
__global__ __launch_bounds__(512) void k_state(
    const float* __restrict__ rnn_state, const float* __restrict__ conv_state,
    const float* __restrict__ conv_w,    const float* __restrict__ conv_b,
    const float* __restrict__ A_log,     const float* __restrict__ dt_bias,
    const float* __restrict__ norm_w,
    float* __restrict__ state_out,       float* __restrict__ conv_out)
{
    extern __shared__ float4 Ssm[];            // 4096 float4 = 64 KB
    const int h    = blockIdx.x;
    const int t    = threadIdx.x;
    const int lane = t & 31;
    const int grp  = t >> 5;                   // 0..15

    __shared__ float  kn_sh[DDIM];
    __shared__ float  qn_sh[DDIM];
    __shared__ float  v_sh[DDIM];
    __shared__ float4 part[16][32];
    __shared__ float4 delta4_sh[32];
    __shared__ float  red[32];

    // ---- independent prologue: stage S (overlaps matvec_in's tail) ----
    const float4* S4 = reinterpret_cast<const float4*>(rnn_state + (size_t)h * DDIM * DDIM);
#pragma unroll
    for (int i = 0; i < 8; i++) Ssm[t + i * 512] = S4[t + i * 512];

    float cs0 = 0.f, cs1 = 0.f, cs2 = 0.f, cw0 = 0.f, cw1 = 0.f, cw2 = 0.f, cw3 = 0.f, cb = 0.f;
    float cs0k = 0.f, cs1k = 0.f, cs2k = 0.f, cw0k = 0.f, cw1k = 0.f, cw2k = 0.f, cw3k = 0.f, cbk = 0.f;
    float cs0v = 0.f, cs1v = 0.f, cs2v = 0.f, cw0v = 0.f, cw1v = 0.f, cw2v = 0.f, cw3v = 0.f, cbv = 0.f;
    int cq = h * DDIM + (t & 127);
    if (t < DDIM) {
        const float* cs = conv_state + (size_t)cq * 3;
        const float* cw = conv_w + (size_t)cq * 4;
        cs0 = cs[0]; cs1 = cs[1]; cs2 = cs[2];
        cw0 = cw[0]; cw1 = cw[1]; cw2 = cw[2]; cw3 = cw[3]; cb = conv_b[cq];
        const float* csk = conv_state + (size_t)(IDIM + cq) * 3;
        const float* cwk = conv_w + (size_t)(IDIM + cq) * 4;
        cs0k = csk[0]; cs1k = csk[1]; cs2k = csk[2];
        cw0k = cwk[0]; cw1k = cwk[1]; cw2k = cwk[2]; cw3k = cwk[3]; cbk = conv_b[IDIM + cq];
        const float* csv = conv_state + (size_t)(2 * IDIM + cq) * 3;
        const float* cwv = conv_w + (size_t)(2 * IDIM + cq) * 4;
        cs0v = csv[0]; cs1v = csv[1]; cs2v = csv[2];
        cw0v = cwv[0]; cw1v = cwv[1]; cw2v = cwv[2]; cw3v = cwv[3]; cbv = conv_b[2 * IDIM + cq];
    }
    float Alog = A_log[h], dtb = dt_bias[h];

    cudaGridDependencySynchronize();
    __syncthreads();

    float q = 0.f, k = 0.f, v = 0.f;
    if (t < DDIM) {
        float xq = g_qkv[cq];
        float xk = g_qkv[IDIM + cq];
        float xv = g_qkv[2 * IDIM + cq];
        q = siluf(cs0 * cw0 + cs1 * cw1 + cs2 * cw2 + xq * cw3 + cb);
        k = siluf(cs0k * cw0k + cs1k * cw1k + cs2k * cw2k + xk * cw3k + cbk);
        v = siluf(cs0v * cw0v + cs1v * cw1v + cs2v * cw2v + xv * cw3v + cbv);
        v_sh[t] = v;
        float* co = conv_out + (size_t)cq * 3;
        co[0] = cs1; co[1] = cs2; co[2] = xq;
        float* cok = conv_out + (size_t)(IDIM + cq) * 3;
        cok[0] = cs1k; cok[1] = cs2k; cok[2] = xk;
        float* cov = conv_out + (size_t)(2 * IDIM + cq) * 3;
        cov[0] = cs1v; cov[1] = cs2v; cov[2] = xv;
    }
    float sq = q * q, sk = k * k;
#pragma unroll
    for (int o = 16; o; o >>= 1) {
        sq += __shfl_down_sync(0xFFFFFFFFu, sq, o);
        sk += __shfl_down_sync(0xFFFFFFFFu, sk, o);
    }
    if (lane == 0) { red[grp] = sq; red[grp + 16] = sk; }
    __syncthreads();
    float sqt = red[0] + red[1] + red[2] + red[3];
    float skt = red[16] + red[17] + red[18] + red[19];
    if (t < DDIM) {
        qn_sh[t] = q / fmaxf(sqrtf(sqt), EPS) * 0.08838834764831845f;
        kn_sh[t] = k / fmaxf(sqrtf(skt), EPS);
    }

    float beta  = 1.f / (1.f + expf(-g_ab[HEADS + h]));
    float arg   = g_ab[h] + dtb;
    float sp    = (arg > 20.f) ? arg : log1pf(expf(arg));
    float decay = expf(-expf(Alog) * sp);
    __syncthreads();

    float4 kv = make_float4(0.f, 0.f, 0.f, 0.f);
#pragma unroll
    for (int j = 0; j < 8; j++) {
        int d = grp * 8 + j;
        float4 s = Ssm[d * 32 + lane];
        float kd = kn_sh[d];
        kv.x += s.x * kd; kv.y += s.y * kd; kv.z += s.z * kd; kv.w += s.w * kd;
    }
    part[grp][lane] = kv;
    __syncthreads();

    if (t < 32) {
        float4 kvt = make_float4(0.f, 0.f, 0.f, 0.f);
#pragma unroll
        for (int g = 0; g < 16; g++) {
            float4 p = part[g][lane];
            kvt.x += p.x; kvt.y += p.y; kvt.z += p.z; kvt.w += p.w;
        }
        float4 d4;
        d4.x = (v_sh[lane * 4 + 0] - kvt.x * decay) * beta;
        d4.y = (v_sh[lane * 4 + 1] - kvt.y * decay) * beta;
        d4.z = (v_sh[lane * 4 + 2] - kvt.z * decay) * beta;
        d4.w = (v_sh[lane * 4 + 3] - kvt.w * decay) * beta;
        delta4_sh[lane] = d4;
    }
    __syncthreads();

    float4* So4 = reinterpret_cast<float4*>(state_out + (size_t)h * DDIM * DDIM);
    float4 delta = delta4_sh[lane];
    float4 core = make_float4(0.f, 0.f, 0.f, 0.f);
#pragma unroll
    for (int j = 0; j < 8; j++) {
        int d = grp * 8 + j;
        float4 s = Ssm[d * 32 + lane];
        float kd = kn_sh[d], qd = qn_sh[d];
        s.x = s.x * decay + kd * delta.x;
        s.y = s.y * decay + kd * delta.y;
        s.z = s.z * decay + kd * delta.z;
        s.w = s.w * decay + kd * delta.w;
        So4[d * 32 + lane] = s;
        core.x += s.x * qd; core.y += s.y * qd; core.z += s.z * qd; core.w += s.w * qd;
    }
    part[grp][lane] = core;

    // dependents (matvec_out) launch now — right before the short finale
    cudaTriggerProgrammaticLaunchCompletion();
    __syncthreads();

    if (t < 32) {
        float4 c = make_float4(0.f, 0.f, 0.f, 0.f);
#pragma unroll
        for (int g = 0; g < 16; g++) {
            float4 p = part[g][lane];
            c.x += p.x; c.y += p.y; c.z += p.z; c.w += p.w;
        }
        float cc = c.x * c.x + c.y * c.y + c.z * c.z + c.w * c.w;
#pragma unroll
        for (int o = 16; o; o >>= 1) cc += __shfl_xor_sync(0xFFFFFFFFu, cc, o);
        float inv = rsqrtf(cc * (1.f / 128.f) + EPS);
        const float4 nw = reinterpret_cast<const float4*>(norm_w)[lane];
        const float4 z4 = reinterpret_cast<const float4*>(g_z + h * DDIM)[lane];
        float4 o4;
        o4.x = nw.x * c.x * inv * siluf(z4.x);
        o4.y = nw.y * c.y * inv * siluf(z4.y);
        o4.z = nw.z * c.z * inv * siluf(z4.z);
        o4.w = nw.w * c.w * inv * siluf(z4.w);
        reinterpret_cast<float4*>(g_pre + h * DDIM)[lane] = o4;
    }
}

// ---------------- kernel 3: output matvec -------------------------------
// Default-policy loads: W_out lines stay in L2 across graph replays (the
// matvec_in stream is __ldcs evict-first and should not displace them), so
// after the first replay this is an L2-hit read.
__global__ __launch_bounds__(256) void k_matvec_out(
    const float* __restrict__ Wout, float* __restrict__ out)
{
    const int t   = threadIdx.x;
    const int rin = t >> 6;          // row within block: 0..3
    const int tr  = t & 63;          // thread within row: 0..63
    const int row = blockIdx.x * 4 + rin;

    const float4* w4 = reinterpret_cast<const float4*>(Wout + (size_t)row * IDIM) + tr;

    float4 buf[16];
#pragma unroll
    for (int j = 0; j < 16; j++) buf[j] = w4[j * 64];

    cudaGridDependencySynchronize();

    __shared__ float4 hs[IDIM / 4];
    __shared__ float  red[8];
    const float4* p4 = reinterpret_cast<const float4*>(g_pre);
    for (int i = t; i < IDIM / 4; i += 256) hs[i] = p4[i];
    __syncthreads();

    float a0 = 0.f, a1 = 0.f, a2 = 0.f, a3 = 0.f;
#pragma unroll
    for (int j = 0; j < 16; j += 4) {
        a0 += dot4(buf[j + 0], hs[tr + (j + 0) * 64]);
        a1 += dot4(buf[j + 1], hs[tr + (j + 1) * 64]);
        a2 += dot4(buf[j + 2], hs[tr + (j + 2) * 64]);
        a3 += dot4(buf[j + 3], hs[tr + (j + 3) * 64]);
    }
    float acc = (a0 + a1) + (a2 + a3);
#pragma unroll
    for (int o = 16; o; o >>= 1) acc += __shfl_down_sync(0xFFFFFFFFu, acc, o);
    int warp = t >> 5, lane = t & 31;
    if (lane == 0) red[warp] = acc;
    __syncthreads();
    if (tr == 0) out[row] = red[rin * 2] + red[rin * 2 + 1];
}

// ---------------- launch ----------------
extern "C" void kernel_launch(void* const* d_in, const int* in_sizes, int n_in,
                              void* d_out, int out_size)
{
    const float* hidden     = (const float*)d_in[0];
    const float* rnn_state  = (const float*)d_in[1];
    const float* conv_state = (const float*)d_in[2];
    const float* W_qkv      = (const float*)d_in[3];
    const float* W_z        = (const float*)d_in[4];
    const float* W_a        = (const float*)d_in[5];
    const float* W_b        = (const float*)d_in[6];
    const float* conv_w     = (const float*)d_in[7];
    const float* conv_b     = (const float*)d_in[8];
    const float* A_log      = (const float*)d_in[9];
    const float* dt_bias    = (const float*)d_in[10];
    const float* norm_w     = (const float*)d_in[11];
    const float* W_out      = (const float*)d_in[12];

    float* out = (float*)d_out;

    float* state_out;
    float* conv_out;
    if (out_size >= IDIM + HEADS * DDIM * DDIM + QKV_ROWS * 3) {
        state_out = out + IDIM;
        conv_out  = out + IDIM + HEADS * DDIM * DDIM;
    } else {
        cudaGetSymbolAddress((void**)&state_out, g_state_scratch);
        cudaGetSymbolAddress((void**)&conv_out,  g_conv_scratch);
    }

    const int STATE_SMEM = 64 * 1024;
    static bool attr_done = false;
    if (!attr_done) {
        cudaFuncSetAttribute(k_state, cudaFuncAttributeMaxDynamicSharedMemorySize, STATE_SMEM);
        attr_done = true;
    }

    k_matvec_in<<<(TOTAL_ROWS + 7) / 8, 256>>>(W_qkv, W_z, W_a, W_b, hidden);

    {
        cudaLaunchConfig_t cfg = {};
        cfg.gridDim  = dim3(HEADS, 1, 1);
        cfg.blockDim = dim3(512, 1, 1);
        cfg.dynamicSmemBytes = STATE_SMEM;
        cfg.stream = 0;
        cudaLaunchAttribute at[1];
        at[0].id = cudaLaunchAttributeProgrammaticStreamSerialization;
        at[0].val.programmaticStreamSerializationAllowed = 1;
        cfg.attrs = at;
        cfg.numAttrs = 1;
        cudaLaunchKernelEx(&cfg, k_state, rnn_state, conv_state, conv_w, conv_b,
                           A_log, dt_bias, norm_w, state_out, conv_out);
    }

    {
        cudaLaunchConfig_t cfg = {};
        cfg.gridDim  = dim3(HID / 4, 1, 1);
        cfg.blockDim = dim3(256, 1, 1);
        cfg.dynamicSmemBytes = 0;
        cfg.stream = 0;
        cudaLaunchAttribute at[1];
        at[0].id = cudaLaunchAttributeProgrammaticStreamSerialization;
        at[0].val.programmaticStreamSerializationAllowed = 1;
        cfg.attrs = at;
        cfg.numAttrs = 1;
        cudaLaunchKernelEx(&cfg, k_matvec_out, W_out, out);
    }
}

// round 9
// speedup vs baseline: 1.2394x; 1.0043x over previous
#include <cuda_runtime.h>
#include <math.h>

#define HID 4096
#define HEADS 32
#define DDIM 128
#define IDIM (HEADS * DDIM)            // 4096
#define QKV_ROWS (3 * IDIM)            // 12288
#define TOTAL_ROWS (QKV_ROWS + IDIM + HEADS + HEADS)  // 16448
#define EPS 1e-6f

// ---------------- scratch (no allocation allowed) ----------------
__device__ float g_qkv[QKV_ROWS];
__device__ float g_z[IDIM];
__device__ float g_ab[2 * HEADS];      // a[0:32], b[32:64]
__device__ float g_pre[IDIM];
__device__ float g_state_scratch[HEADS * DDIM * DDIM];
__device__ float g_conv_scratch[QKV_ROWS * 3];

__device__ __forceinline__ float siluf(float x) { return x / (1.f + expf(-x)); }

__device__ __forceinline__ float dot4(float4 a, float4 b) {
    return a.x * b.x + a.y * b.y + a.z * b.z + a.w * b.w;
}

// ---------------- kernel 1: fused matvec (qkv, z, a, b) -------------------
// PDL trigger at the END: dependents only launch during this kernel's tail.
__global__ __launch_bounds__(256) void k_matvec_in(
    const float* __restrict__ Wqkv, const float* __restrict__ Wz,
    const float* __restrict__ Wa,   const float* __restrict__ Wb,
    const float* __restrict__ h)
{
    __shared__ float4 hs[HID / 4];
    const float4* h4 = reinterpret_cast<const float4*>(h);
    for (int i = threadIdx.x; i < HID / 4; i += 256) hs[i] = h4[i];
    __syncthreads();

    int warp = threadIdx.x >> 5;
    int lane = threadIdx.x & 31;
    int row  = blockIdx.x * 8 + warp;

    if (row < TOTAL_ROWS) {
        const float* W;
        float* outp;
        if (row < QKV_ROWS)              { W = Wqkv + (size_t)row * HID;              outp = g_qkv + row; }
        else if (row < QKV_ROWS + IDIM)  { int r = row - QKV_ROWS; W = Wz + (size_t)r * HID; outp = g_z + r; }
        else if (row < QKV_ROWS + IDIM + HEADS) { int r = row - QKV_ROWS - IDIM; W = Wa + (size_t)r * HID; outp = g_ab + r; }
        else                             { int r = row - QKV_ROWS - IDIM - HEADS; W = Wb + (size_t)r * HID; outp = g_ab + HEADS + r; }

        const float4* w4 = reinterpret_cast<const float4*>(W) + lane;

        float4 buf[4];
#pragma unroll
        for (int j = 0; j < 4; j++) buf[j] = __ldcs(w4 + j * 32);

        float a0 = 0.f, a1 = 0.f, a2 = 0.f, a3 = 0.f;
#pragma unroll
        for (int i = 0; i < 8; i++) {
            float4 c0 = buf[0], c1 = buf[1], c2 = buf[2], c3 = buf[3];
            if (i < 7) {
#pragma unroll
                for (int j = 0; j < 4; j++) buf[j] = __ldcs(w4 + ((i + 1) * 4 + j) * 32);
            }
            a0 += dot4(c0, hs[lane + (i * 4 + 0) * 32]);
            a1 += dot4(c1, hs[lane + (i * 4 + 1) * 32]);
            a2 += dot4(c2, hs[lane + (i * 4 + 2) * 32]);
            a3 += dot4(c3, hs[lane + (i * 4 + 3) * 32]);
        }
        float acc = (a0 + a1) + (a2 + a3);
#pragma unroll
        for (int o = 16; o; o >>= 1) acc += __shfl_down_sync(0xFFFFFFFFu, acc, o);
        if (lane == 0) *outp = acc;
    }

    cudaTriggerProgrammaticLaunchCompletion();
}

// ---------------- kernel 2: conv + gating + state update ----------------
__global__ __launch_bounds__(512) void k_state(
    const float* __restrict__ rnn_state, const float* __restrict__ conv_state,
    const float* __restrict__ conv_w,    const float* __restrict__ conv_b,
    const float* __restrict__ A_log,     const float* __restrict__ dt_bias,
    const float* __restrict__ norm_w,
    float* __restrict__ state_out,       float* __restrict__ conv_out)
{
    extern __shared__ float4 Ssm[];            // 4096 float4 = 64 KB
    const int h    = blockIdx.x;
    const int t    = threadIdx.x;
    const int lane = t & 31;
    const int grp  = t >> 5;                   // 0..15

    __shared__ float  kn_sh[DDIM];
    __shared__ float  qn_sh[DDIM];
    __shared__ float  v_sh[DDIM];
    __shared__ float4 part[16][32];
    __shared__ float4 delta4_sh[32];
    __shared__ float  red[32];

    // ---- independent prologue: stage S (overlaps matvec_in's tail) ----
    const float4* S4 = reinterpret_cast<const float4*>(rnn_state + (size_t)h * DDIM * DDIM);
#pragma unroll
    for (int i = 0; i < 8; i++) Ssm[t + i * 512] = S4[t + i * 512];

    float cs0 = 0.f, cs1 = 0.f, cs2 = 0.f, cw0 = 0.f, cw1 = 0.f, cw2 = 0.f, cw3 = 0.f, cb = 0.f;
    float cs0k = 0.f, cs1k = 0.f, cs2k = 0.f, cw0k = 0.f, cw1k = 0.f, cw2k = 0.f, cw3k = 0.f, cbk = 0.f;
    float cs0v = 0.f, cs1v = 0.f, cs2v = 0.f, cw0v = 0.f, cw1v = 0.f, cw2v = 0.f, cw3v = 0.f, cbv = 0.f;
    int cq = h * DDIM + (t & 127);
    if (t < DDIM) {
        const float* cs = conv_state + (size_t)cq * 3;
        const float* cw = conv_w + (size_t)cq * 4;
        cs0 = cs[0]; cs1 = cs[1]; cs2 = cs[2];
        cw0 = cw[0]; cw1 = cw[1]; cw2 = cw[2]; cw3 = cw[3]; cb = conv_b[cq];
        const float* csk = conv_state + (size_t)(IDIM + cq) * 3;
        const float* cwk = conv_w + (size_t)(IDIM + cq) * 4;
        cs0k = csk[0]; cs1k = csk[1]; cs2k = csk[2];
        cw0k = cwk[0]; cw1k = cwk[1]; cw2k = cwk[2]; cw3k = cwk[3]; cbk = conv_b[IDIM + cq];
        const float* csv = conv_state + (size_t)(2 * IDIM + cq) * 3;
        const float* cwv = conv_w + (size_t)(2 * IDIM + cq) * 4;
        cs0v = csv[0]; cs1v = csv[1]; cs2v = csv[2];
        cw0v = cwv[0]; cw1v = cwv[1]; cw2v = cwv[2]; cw3v = cwv[3]; cbv = conv_b[2 * IDIM + cq];
    }
    float Alog = A_log[h], dtb = dt_bias[h];

    cudaGridDependencySynchronize();
    __syncthreads();

    float q = 0.f, k = 0.f, v = 0.f;
    if (t < DDIM) {
        float xq = g_qkv[cq];
        float xk = g_qkv[IDIM + cq];
        float xv = g_qkv[2 * IDIM + cq];
        q = siluf(cs0 * cw0 + cs1 * cw1 + cs2 * cw2 + xq * cw3 + cb);
        k = siluf(cs0k * cw0k + cs1k * cw1k + cs2k * cw2k + xk * cw3k + cbk);
        v = siluf(cs0v * cw0v + cs1v * cw1v + cs2v * cw2v + xv * cw3v + cbv);
        v_sh[t] = v;
        float* co = conv_out + (size_t)cq * 3;
        co[0] = cs1; co[1] = cs2; co[2] = xq;
        float* cok = conv_out + (size_t)(IDIM + cq) * 3;
        cok[0] = cs1k; cok[1] = cs2k; cok[2] = xk;
        float* cov = conv_out + (size_t)(2 * IDIM + cq) * 3;
        cov[0] = cs1v; cov[1] = cs2v; cov[2] = xv;
    }
    float sq = q * q, sk = k * k;
#pragma unroll
    for (int o = 16; o; o >>= 1) {
        sq += __shfl_down_sync(0xFFFFFFFFu, sq, o);
        sk += __shfl_down_sync(0xFFFFFFFFu, sk, o);
    }
    if (lane == 0) { red[grp] = sq; red[grp + 16] = sk; }
    __syncthreads();
    float sqt = red[0] + red[1] + red[2] + red[3];
    float skt = red[16] + red[17] + red[18] + red[19];
    if (t < DDIM) {
        qn_sh[t] = q / fmaxf(sqrtf(sqt), EPS) * 0.08838834764831845f;
        kn_sh[t] = k / fmaxf(sqrtf(skt), EPS);
    }

    float beta  = 1.f / (1.f + expf(-g_ab[HEADS + h]));
    float arg   = g_ab[h] + dtb;
    float sp    = (arg > 20.f) ? arg : log1pf(expf(arg));
    float decay = expf(-expf(Alog) * sp);
    __syncthreads();

    float4 kv = make_float4(0.f, 0.f, 0.f, 0.f);
#pragma unroll
    for (int j = 0; j < 8; j++) {
        int d = grp * 8 + j;
        float4 s = Ssm[d * 32 + lane];
        float kd = kn_sh[d];
        kv.x += s.x * kd; kv.y += s.y * kd; kv.z += s.z * kd; kv.w += s.w * kd;
    }
    part[grp][lane] = kv;
    __syncthreads();

    if (t < 32) {
        float4 kvt = make_float4(0.f, 0.f, 0.f, 0.f);
#pragma unroll
        for (int g = 0; g < 16; g++) {
            float4 p = part[g][lane];
            kvt.x += p.x; kvt.y += p.y; kvt.z += p.z; kvt.w += p.w;
        }
        float4 d4;
        d4.x = (v_sh[lane * 4 + 0] - kvt.x * decay) * beta;
        d4.y = (v_sh[lane * 4 + 1] - kvt.y * decay) * beta;
        d4.z = (v_sh[lane * 4 + 2] - kvt.z * decay) * beta;
        d4.w = (v_sh[lane * 4 + 3] - kvt.w * decay) * beta;
        delta4_sh[lane] = d4;
    }
    __syncthreads();

    float4* So4 = reinterpret_cast<float4*>(state_out + (size_t)h * DDIM * DDIM);
    float4 delta = delta4_sh[lane];
    float4 core = make_float4(0.f, 0.f, 0.f, 0.f);
#pragma unroll
    for (int j = 0; j < 8; j++) {
        int d = grp * 8 + j;
        float4 s = Ssm[d * 32 + lane];
        float kd = kn_sh[d], qd = qn_sh[d];
        s.x = s.x * decay + kd * delta.x;
        s.y = s.y * decay + kd * delta.y;
        s.z = s.z * decay + kd * delta.z;
        s.w = s.w * decay + kd * delta.w;
        So4[d * 32 + lane] = s;
        core.x += s.x * qd; core.y += s.y * qd; core.z += s.z * qd; core.w += s.w * qd;
    }
    part[grp][lane] = core;

    // dependents (matvec_out) launch now — right before the short finale
    cudaTriggerProgrammaticLaunchCompletion();
    __syncthreads();

    if (t < 32) {
        float4 c = make_float4(0.f, 0.f, 0.f, 0.f);
#pragma unroll
        for (int g = 0; g < 16; g++) {
            float4 p = part[g][lane];
            c.x += p.x; c.y += p.y; c.z += p.z; c.w += p.w;
        }
        float cc = c.x * c.x + c.y * c.y + c.z * c.z + c.w * c.w;
#pragma unroll
        for (int o = 16; o; o >>= 1) cc += __shfl_xor_sync(0xFFFFFFFFu, cc, o);
        float inv = rsqrtf(cc * (1.f / 128.f) + EPS);
        const float4 nw = reinterpret_cast<const float4*>(norm_w)[lane];
        const float4 z4 = reinterpret_cast<const float4*>(g_z + h * DDIM)[lane];
        float4 o4;
        o4.x = nw.x * c.x * inv * siluf(z4.x);
        o4.y = nw.y * c.y * inv * siluf(z4.y);
        o4.z = nw.z * c.z * inv * siluf(z4.z);
        o4.w = nw.w * c.w * inv * siluf(z4.w);
        reinterpret_cast<float4*>(g_pre + h * DDIM)[lane] = o4;
    }
}

// ---------------- kernel 3: output matvec (single-wave grid-stride) ------
// 256 blocks x 256 threads, all resident in one wave (~45 regs, 16KB smem).
// Warp-per-row with stride loop; default/__ldcg loads hit the L2-resident
// W_out (kept warm across graph replays by the __ldcs weight streams).
#define MVOUT_BLOCKS 256
__global__ __launch_bounds__(256) void k_matvec_out(
    const float* __restrict__ Wout, float* __restrict__ out)
{
    cudaGridDependencySynchronize();

    __shared__ float4 hs[IDIM / 4];
    const float4* p4 = reinterpret_cast<const float4*>(g_pre);
    for (int i = threadIdx.x; i < IDIM / 4; i += 256) hs[i] = p4[i];
    __syncthreads();

    int warp = threadIdx.x >> 5;
    int lane = threadIdx.x & 31;

    for (int row = blockIdx.x * 8 + warp; row < HID; row += MVOUT_BLOCKS * 8) {
        const float4* w4 = reinterpret_cast<const float4*>(Wout + (size_t)row * IDIM) + lane;

        float4 buf[4];
#pragma unroll
        for (int j = 0; j < 4; j++) buf[j] = __ldcg(w4 + j * 32);

        float a0 = 0.f, a1 = 0.f, a2 = 0.f, a3 = 0.f;
#pragma unroll
        for (int i = 0; i < 8; i++) {
            float4 c0 = buf[0], c1 = buf[1], c2 = buf[2], c3 = buf[3];
            if (i < 7) {
#pragma unroll
                for (int j = 0; j < 4; j++) buf[j] = __ldcg(w4 + ((i + 1) * 4 + j) * 32);
            }
            a0 += dot4(c0, hs[lane + (i * 4 + 0) * 32]);
            a1 += dot4(c1, hs[lane + (i * 4 + 1) * 32]);
            a2 += dot4(c2, hs[lane + (i * 4 + 2) * 32]);
            a3 += dot4(c3, hs[lane + (i * 4 + 3) * 32]);
        }
        float acc = (a0 + a1) + (a2 + a3);
#pragma unroll
        for (int o = 16; o; o >>= 1) acc += __shfl_down_sync(0xFFFFFFFFu, acc, o);
        if (lane == 0) out[row] = acc;
    }
}

// ---------------- launch ----------------
extern "C" void kernel_launch(void* const* d_in, const int* in_sizes, int n_in,
                              void* d_out, int out_size)
{
    const float* hidden     = (const float*)d_in[0];
    const float* rnn_state  = (const float*)d_in[1];
    const float* conv_state = (const float*)d_in[2];
    const float* W_qkv      = (const float*)d_in[3];
    const float* W_z        = (const float*)d_in[4];
    const float* W_a        = (const float*)d_in[5];
    const float* W_b        = (const float*)d_in[6];
    const float* conv_w     = (const float*)d_in[7];
    const float* conv_b     = (const float*)d_in[8];
    const float* A_log      = (const float*)d_in[9];
    const float* dt_bias    = (const float*)d_in[10];
    const float* norm_w     = (const float*)d_in[11];
    const float* W_out      = (const float*)d_in[12];

    float* out = (float*)d_out;

    float* state_out;
    float* conv_out;
    if (out_size >= IDIM + HEADS * DDIM * DDIM + QKV_ROWS * 3) {
        state_out = out + IDIM;
        conv_out  = out + IDIM + HEADS * DDIM * DDIM;
    } else {
        cudaGetSymbolAddress((void**)&state_out, g_state_scratch);
        cudaGetSymbolAddress((void**)&conv_out,  g_conv_scratch);
    }

    const int STATE_SMEM = 64 * 1024;
    static bool attr_done = false;
    if (!attr_done) {
        cudaFuncSetAttribute(k_state, cudaFuncAttributeMaxDynamicSharedMemorySize, STATE_SMEM);
        attr_done = true;
    }

    k_matvec_in<<<(TOTAL_ROWS + 7) / 8, 256>>>(W_qkv, W_z, W_a, W_b, hidden);

    {
        cudaLaunchConfig_t cfg = {};
        cfg.gridDim  = dim3(HEADS, 1, 1);
        cfg.blockDim = dim3(512, 1, 1);
        cfg.dynamicSmemBytes = STATE_SMEM;
        cfg.stream = 0;
        cudaLaunchAttribute at[1];
        at[0].id = cudaLaunchAttributeProgrammaticStreamSerialization;
        at[0].val.programmaticStreamSerializationAllowed = 1;
        cfg.attrs = at;
        cfg.numAttrs = 1;
        cudaLaunchKernelEx(&cfg, k_state, rnn_state, conv_state, conv_w, conv_b,
                           A_log, dt_bias, norm_w, state_out, conv_out);
    }

    {
        cudaLaunchConfig_t cfg = {};
        cfg.gridDim  = dim3(MVOUT_BLOCKS, 1, 1);
        cfg.blockDim = dim3(256, 1, 1);
        cfg.dynamicSmemBytes = 0;
        cfg.stream = 0;
        cudaLaunchAttribute at[1];
        at[0].id = cudaLaunchAttributeProgrammaticStreamSerialization;
        at[0].val.programmaticStreamSerializationAllowed = 1;
        cfg.attrs = at;
        cfg.numAttrs = 1;
        cudaLaunchKernelEx(&cfg, k_matvec_out, W_out, out);
    }
}

// round 10
// speedup vs baseline: 1.2833x; 1.0354x over previous
#include <cuda_runtime.h>
#include <math.h>

#define HID 4096
#define HEADS 32
#define DDIM 128
#define IDIM (HEADS * DDIM)            // 4096
#define QKV_ROWS (3 * IDIM)            // 12288
#define TOTAL_ROWS (QKV_ROWS + IDIM + HEADS + HEADS)  // 16448
#define EPS 1e-6f

// ---------------- scratch (no allocation allowed) ----------------
__device__ float g_qkv[QKV_ROWS];
__device__ float g_z[IDIM];
__device__ float g_ab[2 * HEADS];      // a[0:32], b[32:64]
__device__ float g_pre[IDIM];
__device__ float g_state_scratch[HEADS * DDIM * DDIM];
__device__ float g_conv_scratch[QKV_ROWS * 3];

__device__ __forceinline__ float siluf(float x) { return x / (1.f + expf(-x)); }

__device__ __forceinline__ float dot4(float4 a, float4 b) {
    return a.x * b.x + a.y * b.y + a.z * b.z + a.w * b.w;
}

// ---------------- kernel 1: fused matvec (qkv, z, a, b) -------------------
// PDL trigger at the END: dependents only launch during this kernel's tail.
__global__ __launch_bounds__(256) void k_matvec_in(
    const float* __restrict__ Wqkv, const float* __restrict__ Wz,
    const float* __restrict__ Wa,   const float* __restrict__ Wb,
    const float* __restrict__ h)
{
    __shared__ float4 hs[HID / 4];
    const float4* h4 = reinterpret_cast<const float4*>(h);
    for (int i = threadIdx.x; i < HID / 4; i += 256) hs[i] = h4[i];
    __syncthreads();

    int warp = threadIdx.x >> 5;
    int lane = threadIdx.x & 31;
    int row  = blockIdx.x * 8 + warp;

    if (row < TOTAL_ROWS) {
        const float* W;
        float* outp;
        if (row < QKV_ROWS)              { W = Wqkv + (size_t)row * HID;              outp = g_qkv + row; }
        else if (row < QKV_ROWS + IDIM)  { int r = row - QKV_ROWS; W = Wz + (size_t)r * HID; outp = g_z + r; }
        else if (row < QKV_ROWS + IDIM + HEADS) { int r = row - QKV_ROWS - IDIM; W = Wa + (size_t)r * HID; outp = g_ab + r; }
        else                             { int r = row - QKV_ROWS - IDIM - HEADS; W = Wb + (size_t)r * HID; outp = g_ab + HEADS + r; }

        const float4* w4 = reinterpret_cast<const float4*>(W) + lane;

        float4 buf[4];
#pragma unroll
        for (int j = 0; j < 4; j++) buf[j] = __ldcs(w4 + j * 32);

        float a0 = 0.f, a1 = 0.f, a2 = 0.f, a3 = 0.f;
#pragma unroll
        for (int i = 0; i < 8; i++) {
            float4 c0 = buf[0], c1 = buf[1], c2 = buf[2], c3 = buf[3];
            if (i < 7) {
#pragma unroll
                for (int j = 0; j < 4; j++) buf[j] = __ldcs(w4 + ((i + 1) * 4 + j) * 32);
            }
            a0 += dot4(c0, hs[lane + (i * 4 + 0) * 32]);
            a1 += dot4(c1, hs[lane + (i * 4 + 1) * 32]);
            a2 += dot4(c2, hs[lane + (i * 4 + 2) * 32]);
            a3 += dot4(c3, hs[lane + (i * 4 + 3) * 32]);
        }
        float acc = (a0 + a1) + (a2 + a3);
#pragma unroll
        for (int o = 16; o; o >>= 1) acc += __shfl_down_sync(0xFFFFFFFFu, acc, o);
        if (lane == 0) *outp = acc;
    }

    cudaTriggerProgrammaticLaunchCompletion();
}

// ---------------- kernel 2: conv + gating + state update ----------------
__global__ __launch_bounds__(512) void k_state(
    const float* __restrict__ rnn_state, const float* __restrict__ conv_state,
    const float* __restrict__ conv_w,    const float* __restrict__ conv_b,
    const float* __restrict__ A_log,     const float* __restrict__ dt_bias,
    const float* __restrict__ norm_w,
    float* __restrict__ state_out,       float* __restrict__ conv_out)
{
    extern __shared__ float4 Ssm[];            // 4096 float4 = 64 KB
    const int h    = blockIdx.x;
    const int t    = threadIdx.x;
    const int lane = t & 31;
    const int grp  = t >> 5;                   // 0..15

    __shared__ float  kn_sh[DDIM];
    __shared__ float  qn_sh[DDIM];
    __shared__ float  v_sh[DDIM];
    __shared__ float4 part[16][32];
    __shared__ float4 delta4_sh[32];
    __shared__ float  red[32];

    // ---- independent prologue: stage S (overlaps matvec_in's tail) ----
    const float4* S4 = reinterpret_cast<const float4*>(rnn_state + (size_t)h * DDIM * DDIM);
#pragma unroll
    for (int i = 0; i < 8; i++) Ssm[t + i * 512] = S4[t + i * 512];

    float cs0 = 0.f, cs1 = 0.f, cs2 = 0.f, cw0 = 0.f, cw1 = 0.f, cw2 = 0.f, cw3 = 0.f, cb = 0.f;
    float cs0k = 0.f, cs1k = 0.f, cs2k = 0.f, cw0k = 0.f, cw1k = 0.f, cw2k = 0.f, cw3k = 0.f, cbk = 0.f;
    float cs0v = 0.f, cs1v = 0.f, cs2v = 0.f, cw0v = 0.f, cw1v = 0.f, cw2v = 0.f, cw3v = 0.f, cbv = 0.f;
    int cq = h * DDIM + (t & 127);
    if (t < DDIM) {
        const float* cs = conv_state + (size_t)cq * 3;
        const float* cw = conv_w + (size_t)cq * 4;
        cs0 = cs[0]; cs1 = cs[1]; cs2 = cs[2];
        cw0 = cw[0]; cw1 = cw[1]; cw2 = cw[2]; cw3 = cw[3]; cb = conv_b[cq];
        const float* csk = conv_state + (size_t)(IDIM + cq) * 3;
        const float* cwk = conv_w + (size_t)(IDIM + cq) * 4;
        cs0k = csk[0]; cs1k = csk[1]; cs2k = csk[2];
        cw0k = cwk[0]; cw1k = cwk[1]; cw2k = cwk[2]; cw3k = cwk[3]; cbk = conv_b[IDIM + cq];
        const float* csv = conv_state + (size_t)(2 * IDIM + cq) * 3;
        const float* cwv = conv_w + (size_t)(2 * IDIM + cq) * 4;
        cs0v = csv[0]; cs1v = csv[1]; cs2v = csv[2];
        cw0v = cwv[0]; cw1v = cwv[1]; cw2v = cwv[2]; cw3v = cwv[3]; cbv = conv_b[2 * IDIM + cq];
    }
    float Alog = A_log[h], dtb = dt_bias[h];

    cudaGridDependencySynchronize();
    __syncthreads();

    float q = 0.f, k = 0.f, v = 0.f;
    if (t < DDIM) {
        float xq = g_qkv[cq];
        float xk = g_qkv[IDIM + cq];
        float xv = g_qkv[2 * IDIM + cq];
        q = siluf(cs0 * cw0 + cs1 * cw1 + cs2 * cw2 + xq * cw3 + cb);
        k = siluf(cs0k * cw0k + cs1k * cw1k + cs2k * cw2k + xk * cw3k + cbk);
        v = siluf(cs0v * cw0v + cs1v * cw1v + cs2v * cw2v + xv * cw3v + cbv);
        v_sh[t] = v;
        float* co = conv_out + (size_t)cq * 3;
        co[0] = cs1; co[1] = cs2; co[2] = xq;
        float* cok = conv_out + (size_t)(IDIM + cq) * 3;
        cok[0] = cs1k; cok[1] = cs2k; cok[2] = xk;
        float* cov = conv_out + (size_t)(2 * IDIM + cq) * 3;
        cov[0] = cs1v; cov[1] = cs2v; cov[2] = xv;
    }
    float sq = q * q, sk = k * k;
#pragma unroll
    for (int o = 16; o; o >>= 1) {
        sq += __shfl_down_sync(0xFFFFFFFFu, sq, o);
        sk += __shfl_down_sync(0xFFFFFFFFu, sk, o);
    }
    if (lane == 0) { red[grp] = sq; red[grp + 16] = sk; }
    __syncthreads();
    float sqt = red[0] + red[1] + red[2] + red[3];
    float skt = red[16] + red[17] + red[18] + red[19];
    if (t < DDIM) {
        qn_sh[t] = q / fmaxf(sqrtf(sqt), EPS) * 0.08838834764831845f;
        kn_sh[t] = k / fmaxf(sqrtf(skt), EPS);
    }

    float beta  = 1.f / (1.f + expf(-g_ab[HEADS + h]));
    float arg   = g_ab[h] + dtb;
    float sp    = (arg > 20.f) ? arg : log1pf(expf(arg));
    float decay = expf(-expf(Alog) * sp);
    __syncthreads();

    float4 kv = make_float4(0.f, 0.f, 0.f, 0.f);
#pragma unroll
    for (int j = 0; j < 8; j++) {
        int d = grp * 8 + j;
        float4 s = Ssm[d * 32 + lane];
        float kd = kn_sh[d];
        kv.x += s.x * kd; kv.y += s.y * kd; kv.z += s.z * kd; kv.w += s.w * kd;
    }
    part[grp][lane] = kv;

    // dependents (matvec_out) can launch now — the remaining work is short
    cudaTriggerProgrammaticLaunchCompletion();
    __syncthreads();

    if (t < 32) {
        float4 kvt = make_float4(0.f, 0.f, 0.f, 0.f);
#pragma unroll
        for (int g = 0; g < 16; g++) {
            float4 p = part[g][lane];
            kvt.x += p.x; kvt.y += p.y; kvt.z += p.z; kvt.w += p.w;
        }
        float4 d4;
        d4.x = (v_sh[lane * 4 + 0] - kvt.x * decay) * beta;
        d4.y = (v_sh[lane * 4 + 1] - kvt.y * decay) * beta;
        d4.z = (v_sh[lane * 4 + 2] - kvt.z * decay) * beta;
        d4.w = (v_sh[lane * 4 + 3] - kvt.w * decay) * beta;
        delta4_sh[lane] = d4;
    }
    __syncthreads();

    float4* So4 = reinterpret_cast<float4*>(state_out + (size_t)h * DDIM * DDIM);
    float4 delta = delta4_sh[lane];
    float4 core = make_float4(0.f, 0.f, 0.f, 0.f);
#pragma unroll
    for (int j = 0; j < 8; j++) {
        int d = grp * 8 + j;
        float4 s = Ssm[d * 32 + lane];
        float kd = kn_sh[d], qd = qn_sh[d];
        s.x = s.x * decay + kd * delta.x;
        s.y = s.y * decay + kd * delta.y;
        s.z = s.z * decay + kd * delta.z;
        s.w = s.w * decay + kd * delta.w;
        So4[d * 32 + lane] = s;
        core.x += s.x * qd; core.y += s.y * qd; core.z += s.z * qd; core.w += s.w * qd;
    }
    part[grp][lane] = core;
    __syncthreads();

    if (t < 32) {
        float4 c = make_float4(0.f, 0.f, 0.f, 0.f);
#pragma unroll
        for (int g = 0; g < 16; g++) {
            float4 p = part[g][lane];
            c.x += p.x; c.y += p.y; c.z += p.z; c.w += p.w;
        }
        float cc = c.x * c.x + c.y * c.y + c.z * c.z + c.w * c.w;
#pragma unroll
        for (int o = 16; o; o >>= 1) cc += __shfl_xor_sync(0xFFFFFFFFu, cc, o);
        float inv = rsqrtf(cc * (1.f / 128.f) + EPS);
        const float4 nw = reinterpret_cast<const float4*>(norm_w)[lane];
        const float4 z4 = reinterpret_cast<const float4*>(g_z + h * DDIM)[lane];
        float4 o4;
        o4.x = nw.x * c.x * inv * siluf(z4.x);
        o4.y = nw.y * c.y * inv * siluf(z4.y);
        o4.z = nw.z * c.z * inv * siluf(z4.z);
        o4.w = nw.w * c.w * inv * siluf(z4.w);
        reinterpret_cast<float4*>(g_pre + h * DDIM)[lane] = o4;
    }
}

// ---------------- kernel 3: output matvec (single wave, full machine) ----
// 512 blocks x 8 warps = 4096 rows, one warp per row, direct mapping.
// ~3.5 blocks/SM in a single wave -> ~28 warps/SM of load concurrency.
#define MVOUT_BLOCKS 512
__global__ __launch_bounds__(256) void k_matvec_out(
    const float* __restrict__ Wout, float* __restrict__ out)
{
    cudaGridDependencySynchronize();

    __shared__ float4 hs[IDIM / 4];
    const float4* p4 = reinterpret_cast<const float4*>(g_pre);
    for (int i = threadIdx.x; i < IDIM / 4; i += 256) hs[i] = p4[i];
    __syncthreads();

    int warp = threadIdx.x >> 5;
    int lane = threadIdx.x & 31;
    int row  = blockIdx.x * 8 + warp;

    const float4* w4 = reinterpret_cast<const float4*>(Wout + (size_t)row * IDIM) + lane;

    float4 buf[4];
#pragma unroll
    for (int j = 0; j < 4; j++) buf[j] = __ldcg(w4 + j * 32);

    float a0 = 0.f, a1 = 0.f, a2 = 0.f, a3 = 0.f;
#pragma unroll
    for (int i = 0; i < 8; i++) {
        float4 c0 = buf[0], c1 = buf[1], c2 = buf[2], c3 = buf[3];
        if (i < 7) {
#pragma unroll
            for (int j = 0; j < 4; j++) buf[j] = __ldcg(w4 + ((i + 1) * 4 + j) * 32);
        }
        a0 += dot4(c0, hs[lane + (i * 4 + 0) * 32]);
        a1 += dot4(c1, hs[lane + (i * 4 + 1) * 32]);
        a2 += dot4(c2, hs[lane + (i * 4 + 2) * 32]);
        a3 += dot4(c3, hs[lane + (i * 4 + 3) * 32]);
    }
    float acc = (a0 + a1) + (a2 + a3);
#pragma unroll
    for (int o = 16; o; o >>= 1) acc += __shfl_down_sync(0xFFFFFFFFu, acc, o);
    if (lane == 0) out[row] = acc;
}

// ---------------- launch ----------------
extern "C" void kernel_launch(void* const* d_in, const int* in_sizes, int n_in,
                              void* d_out, int out_size)
{
    const float* hidden     = (const float*)d_in[0];
    const float* rnn_state  = (const float*)d_in[1];
    const float* conv_state = (const float*)d_in[2];
    const float* W_qkv      = (const float*)d_in[3];
    const float* W_z        = (const float*)d_in[4];
    const float* W_a        = (const float*)d_in[5];
    const float* W_b        = (const float*)d_in[6];
    const float* conv_w     = (const float*)d_in[7];
    const float* conv_b     = (const float*)d_in[8];
    const float* A_log      = (const float*)d_in[9];
    const float* dt_bias    = (const float*)d_in[10];
    const float* norm_w     = (const float*)d_in[11];
    const float* W_out      = (const float*)d_in[12];

    float* out = (float*)d_out;

    float* state_out;
    float* conv_out;
    if (out_size >= IDIM + HEADS * DDIM * DDIM + QKV_ROWS * 3) {
        state_out = out + IDIM;
        conv_out  = out + IDIM + HEADS * DDIM * DDIM;
    } else {
        cudaGetSymbolAddress((void**)&state_out, g_state_scratch);
        cudaGetSymbolAddress((void**)&conv_out,  g_conv_scratch);
    }

    const int STATE_SMEM = 64 * 1024;
    static bool attr_done = false;
    if (!attr_done) {
        cudaFuncSetAttribute(k_state, cudaFuncAttributeMaxDynamicSharedMemorySize, STATE_SMEM);
        attr_done = true;
    }

    k_matvec_in<<<(TOTAL_ROWS + 7) / 8, 256>>>(W_qkv, W_z, W_a, W_b, hidden);

    {
        cudaLaunchConfig_t cfg = {};
        cfg.gridDim  = dim3(HEADS, 1, 1);
        cfg.blockDim = dim3(512, 1, 1);
        cfg.dynamicSmemBytes = STATE_SMEM;
        cfg.stream = 0;
        cudaLaunchAttribute at[1];
        at[0].id = cudaLaunchAttributeProgrammaticStreamSerialization;
        at[0].val.programmaticStreamSerializationAllowed = 1;
        cfg.attrs = at;
        cfg.numAttrs = 1;
        cudaLaunchKernelEx(&cfg, k_state, rnn_state, conv_state, conv_w, conv_b,
                           A_log, dt_bias, norm_w, state_out, conv_out);
    }

    {
        cudaLaunchConfig_t cfg = {};
        cfg.gridDim  = dim3(MVOUT_BLOCKS, 1, 1);
        cfg.blockDim = dim3(256, 1, 1);
        cfg.dynamicSmemBytes = 0;
        cfg.stream = 0;
        cudaLaunchAttribute at[1];
        at[0].id = cudaLaunchAttributeProgrammaticStreamSerialization;
        at[0].val.programmaticStreamSerializationAllowed = 1;
        cfg.attrs = at;
        cfg.numAttrs = 1;
        cudaLaunchKernelEx(&cfg, k_matvec_out, W_out, out);
    }
}